// round 13
// baseline (speedup 1.0000x reference)
#include <cuda_runtime.h>
#include <cuda_fp16.h>
#include <cstdint>

// Stickbreaking attention via mma.sync (HMMA) fp16-split. B=2 H=16 S=1024 D=64.
// Prepass converts K (fp16 hi/lo split) and V (fp16) into pre-swizzled 8KB tile
// images in __device__ scratch; main kernel streams tiles gmem->smem via
// cp.async (double-buffered, 1 barrier/iter) with zero in-loop conversion.
// QK: 3 passes (qh*kh, ql*kh, qh*kl); PV: 1 pass (W,V single fp16).

#define SEQ 1024
#define DH 64
#define BQ 64
#define BK 64
#define THREADS 128
#define NQB (SEQ / BQ)
#define FULL 0xffffffffu

#define KH_O 0
#define KL_O 8192
#define V_O  16384
#define BUFSZ 24576
#define QH_O 49152
#define QL_O 57344
#define SM_TOTAL 65536

__device__ __align__(16) unsigned char g_kh[512 * 8192];
__device__ __align__(16) unsigned char g_kl[512 * 8192];
__device__ __align__(16) unsigned char g_vv[512 * 8192];

__device__ __forceinline__ uint32_t smem_u32(const void* p) {
    uint32_t a;
    asm("{ .reg .u64 t; cvta.to.shared.u64 t, %1; cvt.u32.u64 %0, t; }" : "=r"(a) : "l"(p));
    return a;
}
__device__ __forceinline__ float ex2f(float x) {
    float r; asm("ex2.approx.f32 %0, %1;" : "=f"(r) : "f"(x)); return r;
}
__device__ __forceinline__ float rcpf(float x) {
    float r; asm("rcp.approx.f32 %0, %1;" : "=f"(r) : "f"(x)); return r;
}
__device__ __forceinline__ void cp16(uint32_t dst, const void* src) {
    asm volatile("cp.async.cg.shared.global [%0], [%1], 16;" :: "r"(dst), "l"(src));
}

#define MMA(d, a, b0, b1) \
    asm volatile("mma.sync.aligned.m16n8k16.row.col.f32.f16.f16.f32 " \
        "{%0,%1,%2,%3}, {%4,%5,%6,%7}, {%8,%9}, {%0,%1,%2,%3};" \
        : "+f"((d)[0]), "+f"((d)[1]), "+f"((d)[2]), "+f"((d)[3]) \
        : "r"((a)[0]), "r"((a)[1]), "r"((a)[2]), "r"((a)[3]), "r"(b0), "r"(b1))

#define LDSM4(r, addr) \
    asm volatile("ldmatrix.sync.aligned.m8n8.x4.shared.b16 {%0,%1,%2,%3}, [%4];" \
        : "=r"((r)[0]), "=r"((r)[1]), "=r"((r)[2]), "=r"((r)[3]) : "r"(addr))

#define LDSM4T(r, addr) \
    asm volatile("ldmatrix.sync.aligned.m8n8.x4.trans.shared.b16 {%0,%1,%2,%3}, [%4];" \
        : "=r"((r)[0]), "=r"((r)[1]), "=r"((r)[2]), "=r"((r)[3]) : "r"(addr))

__device__ __forceinline__ uint32_t pack2(__half lo, __half hi) {
    __half2 t(lo, hi);
    return *reinterpret_cast<uint32_t*>(&t);
}
__device__ __forceinline__ void split2(float x, __half& h, __half& l) {
    h = __float2half_rn(x);
    l = __float2half_rn(x - __half2float(h));
}

// ---- prepass: convert K (hi/lo) and V (fp16) into pre-swizzled tile images ----
__global__ __launch_bounds__(THREADS)
void prep(const float* __restrict__ k, const float* __restrict__ v) {
    const int tid = threadIdx.x;
    const int bx = blockIdx.x;           // bh*16 + kb
    const int bh = bx >> 4, kb = bx & 15;
    const size_t tile = (size_t)bx * 8192;
    const float4* gk = (const float4*)(k + ((size_t)bh * SEQ + kb * 64) * DH);
    const float4* gv = (const float4*)(v + ((size_t)bh * SEQ + kb * 64) * DH);
    #pragma unroll
    for (int i = 0; i < 8; i++) {
        int f = i * THREADS + tid;
        int row = f >> 4, c4 = f & 15;
        uint32_t off = (uint32_t)(row * 128 + (((c4 >> 1) ^ (row & 7)) << 4) + (c4 & 1) * 8);
        float4 kx = gk[f];
        __half h0, h1, h2, h3, l0, l1, l2, l3;
        split2(kx.x, h0, l0); split2(kx.y, h1, l1);
        split2(kx.z, h2, l2); split2(kx.w, h3, l3);
        *(uint2*)(g_kh + tile + off) = make_uint2(pack2(h0, h1), pack2(h2, h3));
        *(uint2*)(g_kl + tile + off) = make_uint2(pack2(l0, l1), pack2(l2, l3));
        float4 vx = gv[f];
        __half v0 = __float2half_rn(vx.x), v1 = __float2half_rn(vx.y);
        __half v2 = __float2half_rn(vx.z), v3 = __float2half_rn(vx.w);
        *(uint2*)(g_vv + tile + off) = make_uint2(pack2(v0, v1), pack2(v2, v3));
    }
}

// issue cp.async for one 24KB tile set (KH,KL,V) into smem buffer base
__device__ __forceinline__ void fetch_tiles(uint32_t bufb, size_t tile, int tid) {
    #pragma unroll
    for (int i = 0; i < 4; i++) {
        uint32_t c = (uint32_t)(i * 2048 + tid * 16);
        cp16(bufb + KH_O + c, g_kh + tile + c);
        cp16(bufb + KL_O + c, g_kl + tile + c);
        cp16(bufb + V_O  + c, g_vv + tile + c);
    }
    asm volatile("cp.async.commit_group;" ::: "memory");
}

__global__ __launch_bounds__(THREADS)
void sb_mma(const float* __restrict__ q, const float* __restrict__ v_unused,
            float* __restrict__ out) {
    extern __shared__ __align__(16) char smem[];
    const uint32_t sb = smem_u32(smem);
    const int tid = threadIdx.x;
    const int lane = tid & 31, warp = tid >> 5;
    const int q4 = lane & 3;                     // quad col idx
    const int sel = lane >> 3, rr = lane & 7;    // ldmatrix select / row

    const int idx = blockIdx.x;
    const int qb = (NQB - 1) - (idx >> 5);       // heaviest q-tiles first
    const int bh = idx & 31;
    const int qbase = qb * BQ;

    const float* qg = q + (size_t)bh * SEQ * DH;
    float* og = out + (size_t)bh * SEQ * DH;

    // ---- kick off cp.async for the first (diagonal) tile set into buf0 ----
    fetch_tiles(sb, (size_t)(bh * 16 + qb) * 8192, tid);

    // ---- stage Q tile (fp16 hi/lo) into QH/QL, XOR-swizzled ----
    {
        const float4* gq = (const float4*)(qg + (size_t)qbase * DH);
        #pragma unroll
        for (int i = 0; i < 8; i++) {
            int f = i * THREADS + tid;
            int row = f >> 4, c4 = f & 15;
            float4 x = gq[f];
            __half h0, h1, h2, h3, l0, l1, l2, l3;
            split2(x.x, h0, l0); split2(x.y, h1, l1);
            split2(x.z, h2, l2); split2(x.w, h3, l3);
            uint32_t off = (uint32_t)(row * 128 + (((c4 >> 1) ^ (row & 7)) << 4) + (c4 & 1) * 8);
            *(uint2*)(smem + QH_O + off) = make_uint2(pack2(h0, h1), pack2(h2, h3));
            *(uint2*)(smem + QL_O + off) = make_uint2(pack2(l0, l1), pack2(l2, l3));
        }
    }
    __syncthreads();

    // ---- persistent Q A-fragments (hi & lo); QH/QL never overwritten ----
    uint32_t qh[4][4], ql[4][4];
    {
        int row = warp * 16 + (sel & 1) * 8 + rr;
        #pragma unroll
        for (int kc = 0; kc < 4; kc++) {
            int chunk = 2 * kc + (sel >> 1);
            uint32_t a = sb + (uint32_t)(row * 128 + ((chunk ^ rr) << 4));
            LDSM4(qh[kc], a + QH_O);
            LDSM4(ql[kc], a + QL_O);
        }
    }

    float o[8][4];
    #pragma unroll
    for (int nt = 0; nt < 8; nt++) { o[nt][0] = o[nt][1] = o[nt][2] = o[nt][3] = 0.f; }
    float P0 = 1.f, P1 = 1.f;                    // multiplicative carries
    const int wr0 = qbase + warp * 16 + (lane >> 2);
    const float SC = 0.18033688f;                // 0.125 * log2(e)

    #pragma unroll 1
    for (int kb = qb; kb >= 0; --kb) {
        const int kbase = kb * BK;
        const uint32_t bsb = sb + (uint32_t)(((qb - kb) & 1) ? BUFSZ : 0);

        asm volatile("cp.async.wait_group 0;" ::: "memory");
        __syncthreads();   // current buf filled for all; prev buf reads all done

        // -- issue next tile set into the other buffer (covered by full body) --
        if (kb > 0)
            fetch_tiles(sb + (uint32_t)(((qb - kb) & 1) ? 0 : BUFSZ),
                        (size_t)(bh * 16 + kb - 1) * 8192, tid);

        // ---- QK^T: D[16 rows x 64 keys], 3 split passes ----
        float d[8][4];
        #pragma unroll
        for (int nt = 0; nt < 8; nt++) { d[nt][0] = d[nt][1] = d[nt][2] = d[nt][3] = 0.f; }

        #pragma unroll
        for (int kc = 0; kc < 4; kc++) {
            uint32_t kf[16];
            const int keyl = (sel >> 1) * 8 + rr;
            const int chunk = 2 * kc + (sel & 1);
            #pragma unroll
            for (int p = 0; p < 4; p++) {
                uint32_t a = bsb + KH_O + (uint32_t)((p * 16 + keyl) * 128 + ((chunk ^ rr) << 4));
                LDSM4(&kf[p * 4], a);
            }
            #pragma unroll
            for (int nt = 0; nt < 8; nt++) MMA(d[nt], qh[kc], kf[nt * 2], kf[nt * 2 + 1]);
            #pragma unroll
            for (int nt = 0; nt < 8; nt++) MMA(d[nt], ql[kc], kf[nt * 2], kf[nt * 2 + 1]);
            #pragma unroll
            for (int p = 0; p < 4; p++) {
                uint32_t a = bsb + KL_O + (uint32_t)((p * 16 + keyl) * 128 + ((chunk ^ rr) << 4));
                LDSM4(&kf[p * 4], a);
            }
            #pragma unroll
            for (int nt = 0; nt < 8; nt++) MMA(d[nt], qh[kc], kf[nt * 2], kf[nt * 2 + 1]);
        }

        // ---- stickbreaking scan: linear domain, suffix product over quad ----
        uint32_t wa_[4][4];
        const bool diag = (kb == qb);
        #pragma unroll
        for (int nt = 7; nt >= 0; --nt) {
            const int keyA = kbase + nt * 8 + 2 * q4;
            #pragma unroll
            for (int rs = 0; rs < 2; rs++) {
                float x2a = d[nt][rs * 2 + 0] * SC;
                float x2b = d[nt][rs * 2 + 1] * SC;
                float ta = ex2f(-x2a), tb = ex2f(-x2b);
                float za = rcpf(1.f + ta), zb = rcpf(1.f + tb);
                float ba = 1.f - za, bb = 1.f - zb;
                if (diag) {
                    const int rowg = wr0 + rs * 8;
                    if (keyA > rowg)     { za = 0.f; ba = 1.f; }
                    if (keyA + 1 > rowg) { zb = 0.f; bb = 1.f; }
                }
                float pp = ba * bb;
                float u = pp;                               // inclusive suffix product
                float t1 = __shfl_down_sync(FULL, u, 1, 4);
                u = (q4 < 3) ? u * t1 : u;
                float t2 = __shfl_down_sync(FULL, u, 2, 4);
                u = (q4 < 2) ? u * t2 : u;
                float ue = __shfl_down_sync(FULL, u, 1, 4); // exclusive (lanes above)
                ue = (q4 < 3) ? ue : 1.f;
                float tot = __shfl_sync(FULL, u, 0, 4);
                float& P = rs ? P1 : P0;
                float R  = P * ue;                          // betas of all higher keys
                float Rb = bb * R;
                float wb = zb * Rb;
                float wa = za * ba * Rb;
                P *= tot;
                wa_[nt >> 1][(nt & 1) * 2 + rs] =
                    pack2(__float2half_rn(wa), __float2half_rn(wb));
            }
        }

        // ---- PV: O += W * V (single pass, V via ldmatrix.trans) ----
        #pragma unroll
        for (int kc = 0; kc < 4; kc++) {
            uint32_t vf[16];
            const int keyv = kc * 16 + (sel & 1) * 8 + rr;
            #pragma unroll
            for (int p = 0; p < 4; p++) {
                int chunk = 2 * p + (sel >> 1);
                uint32_t a = bsb + V_O + (uint32_t)(keyv * 128 + ((chunk ^ rr) << 4));
                LDSM4T(&vf[p * 4], a);
            }
            #pragma unroll
            for (int nt = 0; nt < 8; nt++) MMA(o[nt], wa_[kc], vf[nt * 2], vf[nt * 2 + 1]);
        }
    }

    // ---- write output: per-thread 2 rows x 16 cols as float2 ----
    {
        float* r0p = og + (size_t)wr0 * DH;
        float* r1p = og + (size_t)(wr0 + 8) * DH;
        #pragma unroll
        for (int nt = 0; nt < 8; nt++) {
            *(float2*)(r0p + nt * 8 + 2 * q4) = make_float2(o[nt][0], o[nt][1]);
            *(float2*)(r1p + nt * 8 + 2 * q4) = make_float2(o[nt][2], o[nt][3]);
        }
    }
    (void)v_unused;
}

extern "C" void kernel_launch(void* const* d_in, const int* in_sizes, int n_in,
                              void* d_out, int out_size) {
    const float* q = (const float*)d_in[0];
    const float* k = (const float*)d_in[1];
    const float* v = (const float*)d_in[2];
    float* out = (float*)d_out;
    (void)in_sizes; (void)n_in; (void)out_size;

    prep<<<512, THREADS>>>(k, v);   // pre-split/swizzle K,V tiles into scratch

    cudaFuncSetAttribute(sb_mma, cudaFuncAttributeMaxDynamicSharedMemorySize, SM_TOTAL);
    sb_mma<<<NQB * 32, THREADS, SM_TOTAL>>>(q, v, out);  // 512 CTAs, heaviest first
}

// round 14
// speedup vs baseline: 1.0413x; 1.0413x over previous
#include <cuda_runtime.h>
#include <cuda_fp16.h>
#include <cstdint>

// Stickbreaking attention via mma.sync (HMMA) fp16-split. B=2 H=16 S=1024 D=64.
// Critical-path split: heavy q-tiles (qb>=8) run as TWO CTAs:
//   Upper: kb in [8..qb] (incl diag) -> writes partial out + per-row beta-product P_up
//   Lower: kb in [0..7], carry=1     -> writes O_low scratch
// combine: out += P_up * O_low. Max chain 16 -> 8 key-block iterations.
// Prepass pre-splits K (fp16 hi/lo) + V (fp16) into swizzled tile images.

#define SEQ 1024
#define DH 64
#define BQ 64
#define BK 64
#define THREADS 128
#define NQB (SEQ / BQ)
#define FULL 0xffffffffu

#define KH_O 0
#define KL_O 8192
#define V_O  16384
#define BUFSZ 24576
#define QH_O 49152
#define QL_O 57344
#define SM_TOTAL 65536

__device__ __align__(16) unsigned char g_kh[512 * 8192];
__device__ __align__(16) unsigned char g_kl[512 * 8192];
__device__ __align__(16) unsigned char g_vv[512 * 8192];
__device__ __align__(16) float g_olow[32 * 512 * 64];
__device__ __align__(16) float g_pup[32 * 512];

__device__ __forceinline__ uint32_t smem_u32(const void* p) {
    uint32_t a;
    asm("{ .reg .u64 t; cvta.to.shared.u64 t, %1; cvt.u32.u64 %0, t; }" : "=r"(a) : "l"(p));
    return a;
}
__device__ __forceinline__ float ex2f(float x) {
    float r; asm("ex2.approx.f32 %0, %1;" : "=f"(r) : "f"(x)); return r;
}
__device__ __forceinline__ float rcpf(float x) {
    float r; asm("rcp.approx.f32 %0, %1;" : "=f"(r) : "f"(x)); return r;
}
__device__ __forceinline__ void cp16(uint32_t dst, const void* src) {
    asm volatile("cp.async.cg.shared.global [%0], [%1], 16;" :: "r"(dst), "l"(src));
}

#define MMA(d, a, b0, b1) \
    asm volatile("mma.sync.aligned.m16n8k16.row.col.f32.f16.f16.f32 " \
        "{%0,%1,%2,%3}, {%4,%5,%6,%7}, {%8,%9}, {%0,%1,%2,%3};" \
        : "+f"((d)[0]), "+f"((d)[1]), "+f"((d)[2]), "+f"((d)[3]) \
        : "r"((a)[0]), "r"((a)[1]), "r"((a)[2]), "r"((a)[3]), "r"(b0), "r"(b1))

#define LDSM4(r, addr) \
    asm volatile("ldmatrix.sync.aligned.m8n8.x4.shared.b16 {%0,%1,%2,%3}, [%4];" \
        : "=r"((r)[0]), "=r"((r)[1]), "=r"((r)[2]), "=r"((r)[3]) : "r"(addr))

#define LDSM4T(r, addr) \
    asm volatile("ldmatrix.sync.aligned.m8n8.x4.trans.shared.b16 {%0,%1,%2,%3}, [%4];" \
        : "=r"((r)[0]), "=r"((r)[1]), "=r"((r)[2]), "=r"((r)[3]) : "r"(addr))

__device__ __forceinline__ uint32_t pack2(__half lo, __half hi) {
    __half2 t(lo, hi);
    return *reinterpret_cast<uint32_t*>(&t);
}
__device__ __forceinline__ void split2(float x, __half& h, __half& l) {
    h = __float2half_rn(x);
    l = __float2half_rn(x - __half2float(h));
}

// ---- prepass: convert K (hi/lo) and V (fp16) into pre-swizzled tile images ----
__global__ __launch_bounds__(THREADS)
void prep(const float* __restrict__ k, const float* __restrict__ v) {
    const int tid = threadIdx.x;
    const int bx = blockIdx.x;           // bh*16 + kb
    const int bh = bx >> 4, kb = bx & 15;
    const size_t tile = (size_t)bx * 8192;
    const float4* gk = (const float4*)(k + ((size_t)bh * SEQ + kb * 64) * DH);
    const float4* gv = (const float4*)(v + ((size_t)bh * SEQ + kb * 64) * DH);
    #pragma unroll
    for (int i = 0; i < 8; i++) {
        int f = i * THREADS + tid;
        int row = f >> 4, c4 = f & 15;
        uint32_t off = (uint32_t)(row * 128 + (((c4 >> 1) ^ (row & 7)) << 4) + (c4 & 1) * 8);
        float4 kx = gk[f];
        __half h0, h1, h2, h3, l0, l1, l2, l3;
        split2(kx.x, h0, l0); split2(kx.y, h1, l1);
        split2(kx.z, h2, l2); split2(kx.w, h3, l3);
        *(uint2*)(g_kh + tile + off) = make_uint2(pack2(h0, h1), pack2(h2, h3));
        *(uint2*)(g_kl + tile + off) = make_uint2(pack2(l0, l1), pack2(l2, l3));
        float4 vx = gv[f];
        __half v0 = __float2half_rn(vx.x), v1 = __float2half_rn(vx.y);
        __half v2 = __float2half_rn(vx.z), v3 = __float2half_rn(vx.w);
        *(uint2*)(g_vv + tile + off) = make_uint2(pack2(v0, v1), pack2(v2, v3));
    }
}

// issue cp.async for one 24KB tile set (KH,KL,V) into smem buffer base
__device__ __forceinline__ void fetch_tiles(uint32_t bufb, size_t tile, int tid) {
    #pragma unroll
    for (int i = 0; i < 4; i++) {
        uint32_t c = (uint32_t)(i * 2048 + tid * 16);
        cp16(bufb + KH_O + c, g_kh + tile + c);
        cp16(bufb + KL_O + c, g_kl + tile + c);
        cp16(bufb + V_O  + c, g_vv + tile + c);
    }
    asm volatile("cp.async.commit_group;" ::: "memory");
}

__global__ __launch_bounds__(THREADS)
void sb_mma(const float* __restrict__ q, float* __restrict__ out) {
    extern __shared__ __align__(16) char smem[];
    const uint32_t sb = smem_u32(smem);
    const int tid = threadIdx.x;
    const int lane = tid & 31, warp = tid >> 5;
    const int q4 = lane & 3;                     // quad col idx
    const int sel = lane >> 3, rr = lane & 7;    // ldmatrix select / row

    // ---- chain-length-descending CTA mapping ----
    // t==0: A qb7 | t 1..8: L qb t+7 | t==9: U qb15 |
    // t 10..23: pairs p=(t-10)/2: even -> A qb 6-p, odd -> U qb 14-p
    const int bh = blockIdx.x & 31;
    const int t = blockIdx.x >> 5;
    int mode, qb;                                 // 0=A (full), 1=U (upper), 2=L (lower)
    if (t == 0)      { mode = 0; qb = 7; }
    else if (t <= 8) { mode = 2; qb = t + 7; }
    else if (t == 9) { mode = 1; qb = 15; }
    else {
        int p = (t - 10) >> 1;
        if (((t - 10) & 1) == 0) { mode = 0; qb = 6 - p; }
        else                     { mode = 1; qb = 14 - p; }
    }
    const int kb_hi = (mode == 2) ? 7 : qb;
    const int kb_lo = (mode == 1) ? 8 : 0;
    const int qbase = qb * BQ;

    const float* qg = q + (size_t)bh * SEQ * DH;

    // ---- kick off cp.async for the first tile set into buf0 ----
    fetch_tiles(sb, (size_t)(bh * 16 + kb_hi) * 8192, tid);

    // ---- stage Q tile (fp16 hi/lo) into QH/QL, XOR-swizzled ----
    {
        const float4* gq = (const float4*)(qg + (size_t)qbase * DH);
        #pragma unroll
        for (int i = 0; i < 8; i++) {
            int f = i * THREADS + tid;
            int row = f >> 4, c4 = f & 15;
            float4 x = gq[f];
            __half h0, h1, h2, h3, l0, l1, l2, l3;
            split2(x.x, h0, l0); split2(x.y, h1, l1);
            split2(x.z, h2, l2); split2(x.w, h3, l3);
            uint32_t off = (uint32_t)(row * 128 + (((c4 >> 1) ^ (row & 7)) << 4) + (c4 & 1) * 8);
            *(uint2*)(smem + QH_O + off) = make_uint2(pack2(h0, h1), pack2(h2, h3));
            *(uint2*)(smem + QL_O + off) = make_uint2(pack2(l0, l1), pack2(l2, l3));
        }
    }
    __syncthreads();

    // ---- persistent Q A-fragments (hi & lo); QH/QL never overwritten ----
    uint32_t qh[4][4], ql[4][4];
    {
        int row = warp * 16 + (sel & 1) * 8 + rr;
        #pragma unroll
        for (int kc = 0; kc < 4; kc++) {
            int chunk = 2 * kc + (sel >> 1);
            uint32_t a = sb + (uint32_t)(row * 128 + ((chunk ^ rr) << 4));
            LDSM4(qh[kc], a + QH_O);
            LDSM4(ql[kc], a + QL_O);
        }
    }

    float o[8][4];
    #pragma unroll
    for (int nt = 0; nt < 8; nt++) { o[nt][0] = o[nt][1] = o[nt][2] = o[nt][3] = 0.f; }
    float P0 = 1.f, P1 = 1.f;                    // multiplicative carries
    const int wr0 = qbase + warp * 16 + (lane >> 2);
    const float SC = 0.18033688f;                // 0.125 * log2(e)

    #pragma unroll 1
    for (int kb = kb_hi; kb >= kb_lo; --kb) {
        const int kbase = kb * BK;
        const uint32_t bsb = sb + (uint32_t)(((kb_hi - kb) & 1) ? BUFSZ : 0);

        asm volatile("cp.async.wait_group 0;" ::: "memory");
        __syncthreads();   // current buf filled for all; prev buf reads all done

        // -- issue next tile set into the other buffer (covered by full body) --
        if (kb > kb_lo)
            fetch_tiles(sb + (uint32_t)(((kb_hi - kb) & 1) ? 0 : BUFSZ),
                        (size_t)(bh * 16 + kb - 1) * 8192, tid);

        // ---- QK^T: D[16 rows x 64 keys], 3 split passes ----
        float d[8][4];
        #pragma unroll
        for (int nt = 0; nt < 8; nt++) { d[nt][0] = d[nt][1] = d[nt][2] = d[nt][3] = 0.f; }

        #pragma unroll
        for (int kc = 0; kc < 4; kc++) {
            uint32_t kf[16];
            const int keyl = (sel >> 1) * 8 + rr;
            const int chunk = 2 * kc + (sel & 1);
            #pragma unroll
            for (int p = 0; p < 4; p++) {
                uint32_t a = bsb + KH_O + (uint32_t)((p * 16 + keyl) * 128 + ((chunk ^ rr) << 4));
                LDSM4(&kf[p * 4], a);
            }
            #pragma unroll
            for (int nt = 0; nt < 8; nt++) MMA(d[nt], qh[kc], kf[nt * 2], kf[nt * 2 + 1]);
            #pragma unroll
            for (int nt = 0; nt < 8; nt++) MMA(d[nt], ql[kc], kf[nt * 2], kf[nt * 2 + 1]);
            #pragma unroll
            for (int p = 0; p < 4; p++) {
                uint32_t a = bsb + KL_O + (uint32_t)((p * 16 + keyl) * 128 + ((chunk ^ rr) << 4));
                LDSM4(&kf[p * 4], a);
            }
            #pragma unroll
            for (int nt = 0; nt < 8; nt++) MMA(d[nt], qh[kc], kf[nt * 2], kf[nt * 2 + 1]);
        }

        // ---- stickbreaking scan: linear domain, suffix product over quad ----
        uint32_t wa_[4][4];
        const bool diag = (kb == qb);
        #pragma unroll
        for (int nt = 7; nt >= 0; --nt) {
            const int keyA = kbase + nt * 8 + 2 * q4;
            #pragma unroll
            for (int rs = 0; rs < 2; rs++) {
                float x2a = d[nt][rs * 2 + 0] * SC;
                float x2b = d[nt][rs * 2 + 1] * SC;
                float ta = ex2f(-x2a), tb = ex2f(-x2b);
                float za = rcpf(1.f + ta), zb = rcpf(1.f + tb);
                float ba = 1.f - za, bb = 1.f - zb;
                if (diag) {
                    const int rowg = wr0 + rs * 8;
                    if (keyA > rowg)     { za = 0.f; ba = 1.f; }
                    if (keyA + 1 > rowg) { zb = 0.f; bb = 1.f; }
                }
                float pp = ba * bb;
                float u = pp;                               // inclusive suffix product
                float t1 = __shfl_down_sync(FULL, u, 1, 4);
                u = (q4 < 3) ? u * t1 : u;
                float t2 = __shfl_down_sync(FULL, u, 2, 4);
                u = (q4 < 2) ? u * t2 : u;
                float ue = __shfl_down_sync(FULL, u, 1, 4); // exclusive (lanes above)
                ue = (q4 < 3) ? ue : 1.f;
                float tot = __shfl_sync(FULL, u, 0, 4);
                float& P = rs ? P1 : P0;
                float R  = P * ue;                          // betas of all higher keys
                float Rb = bb * R;
                float wb = zb * Rb;
                float wa = za * ba * Rb;
                P *= tot;
                wa_[nt >> 1][(nt & 1) * 2 + rs] =
                    pack2(__float2half_rn(wa), __float2half_rn(wb));
            }
        }

        // ---- PV: O += W * V (single pass, V via ldmatrix.trans) ----
        #pragma unroll
        for (int kc = 0; kc < 4; kc++) {
            uint32_t vf[16];
            const int keyv = kc * 16 + (sel & 1) * 8 + rr;
            #pragma unroll
            for (int p = 0; p < 4; p++) {
                int chunk = 2 * p + (sel >> 1);
                uint32_t a = bsb + V_O + (uint32_t)(keyv * 128 + ((chunk ^ rr) << 4));
                LDSM4T(&vf[p * 4], a);
            }
            #pragma unroll
            for (int nt = 0; nt < 8; nt++) MMA(o[nt], wa_[kc], vf[nt * 2], vf[nt * 2 + 1]);
        }
    }

    // ---- write results ----
    if (mode == 2) {
        // Lower half: O_low to scratch (rows wr0, wr0+8 are >= 512)
        float* r0p = g_olow + ((size_t)bh * 512 + (wr0 - 512)) * DH;
        float* r1p = g_olow + ((size_t)bh * 512 + (wr0 - 512 + 8)) * DH;
        #pragma unroll
        for (int nt = 0; nt < 8; nt++) {
            *(float2*)(r0p + nt * 8 + 2 * q4) = make_float2(o[nt][0], o[nt][1]);
            *(float2*)(r1p + nt * 8 + 2 * q4) = make_float2(o[nt][2], o[nt][3]);
        }
    } else {
        float* og = out + (size_t)bh * SEQ * DH;
        float* r0p = og + (size_t)wr0 * DH;
        float* r1p = og + (size_t)(wr0 + 8) * DH;
        #pragma unroll
        for (int nt = 0; nt < 8; nt++) {
            *(float2*)(r0p + nt * 8 + 2 * q4) = make_float2(o[nt][0], o[nt][1]);
            *(float2*)(r1p + nt * 8 + 2 * q4) = make_float2(o[nt][2], o[nt][3]);
        }
        if (mode == 1 && q4 == 0) {
            // Upper half: per-row beta products for the combine
            g_pup[bh * 512 + (wr0 - 512)] = P0;
            g_pup[bh * 512 + (wr0 - 512 + 8)] = P1;
        }
    }
}

// ---- combine: out[rows 512..1023] += P_up * O_low ----
__global__ __launch_bounds__(THREADS)
void comb(float* __restrict__ out) {
    const int x = blockIdx.x;            // bh*64 + rowgroup(8 rows)
    const int bh = x >> 6, rg = x & 63;
    const int tid = threadIdx.x;
    const int rl = tid >> 4, c = tid & 15;      // 8 rows x 16 float4-cols
    const int row = rg * 8 + rl;                // 0..511 local
    const float p = g_pup[bh * 512 + row];
    const float4 ol = ((const float4*)(g_olow + ((size_t)bh * 512 + row) * DH))[c];
    float4* op = (float4*)(out + ((size_t)bh * SEQ + 512 + row) * DH) + c;
    float4 ov = *op;
    ov.x += p * ol.x; ov.y += p * ol.y; ov.z += p * ol.z; ov.w += p * ol.w;
    *op = ov;
}

extern "C" void kernel_launch(void* const* d_in, const int* in_sizes, int n_in,
                              void* d_out, int out_size) {
    const float* q = (const float*)d_in[0];
    const float* k = (const float*)d_in[1];
    const float* v = (const float*)d_in[2];
    float* out = (float*)d_out;
    (void)in_sizes; (void)n_in; (void)out_size;

    prep<<<512, THREADS>>>(k, v);   // pre-split/swizzle K,V tiles into scratch

    cudaFuncSetAttribute(sb_mma, cudaFuncAttributeMaxDynamicSharedMemorySize, SM_TOTAL);
    sb_mma<<<24 * 32, THREADS, SM_TOTAL>>>(q, out);   // 768 CTAs, longest chains first

    comb<<<32 * 64, THREADS>>>(out);  // merge split halves
}

// round 15
// speedup vs baseline: 1.0449x; 1.0035x over previous
#include <cuda_runtime.h>
#include <cuda_fp16.h>
#include <cstdint>

// Stickbreaking attention via mma.sync (HMMA) fp16-split. B=2 H=16 S=1024 D=64.
// Critical-path split: heavy q-tiles (qb>=8) run as TWO CTAs (Upper incl diag,
// Lower kb 0..7); comb: out += P_up * O_low (O_low stored fp16).
// Prepass pre-splits K (fp16 hi/lo) + V (fp16) into swizzled tile images.
// Main loop interleaves the suffix-product scan (MUFU) with PV MMAs per kc.

#define SEQ 1024
#define DH 64
#define BQ 64
#define BK 64
#define THREADS 128
#define NQB (SEQ / BQ)
#define FULL 0xffffffffu

#define KH_O 0
#define KL_O 8192
#define V_O  16384
#define BUFSZ 24576
#define QH_O 49152
#define QL_O 57344
#define SM_TOTAL 65536

__device__ __align__(16) unsigned char g_kh[512 * 8192];
__device__ __align__(16) unsigned char g_kl[512 * 8192];
__device__ __align__(16) unsigned char g_vv[512 * 8192];
__device__ __align__(16) __half g_olow[32 * 512 * 64];
__device__ __align__(16) float g_pup[32 * 512];

__device__ __forceinline__ uint32_t smem_u32(const void* p) {
    uint32_t a;
    asm("{ .reg .u64 t; cvta.to.shared.u64 t, %1; cvt.u32.u64 %0, t; }" : "=r"(a) : "l"(p));
    return a;
}
__device__ __forceinline__ float ex2f(float x) {
    float r; asm("ex2.approx.f32 %0, %1;" : "=f"(r) : "f"(x)); return r;
}
__device__ __forceinline__ float rcpf(float x) {
    float r; asm("rcp.approx.f32 %0, %1;" : "=f"(r) : "f"(x)); return r;
}
__device__ __forceinline__ void cp16(uint32_t dst, const void* src) {
    asm volatile("cp.async.cg.shared.global [%0], [%1], 16;" :: "r"(dst), "l"(src));
}

#define MMA(d, a, b0, b1) \
    asm volatile("mma.sync.aligned.m16n8k16.row.col.f32.f16.f16.f32 " \
        "{%0,%1,%2,%3}, {%4,%5,%6,%7}, {%8,%9}, {%0,%1,%2,%3};" \
        : "+f"((d)[0]), "+f"((d)[1]), "+f"((d)[2]), "+f"((d)[3]) \
        : "r"((a)[0]), "r"((a)[1]), "r"((a)[2]), "r"((a)[3]), "r"(b0), "r"(b1))

#define LDSM4(r, addr) \
    asm volatile("ldmatrix.sync.aligned.m8n8.x4.shared.b16 {%0,%1,%2,%3}, [%4];" \
        : "=r"((r)[0]), "=r"((r)[1]), "=r"((r)[2]), "=r"((r)[3]) : "r"(addr))

#define LDSM4T(r, addr) \
    asm volatile("ldmatrix.sync.aligned.m8n8.x4.trans.shared.b16 {%0,%1,%2,%3}, [%4];" \
        : "=r"((r)[0]), "=r"((r)[1]), "=r"((r)[2]), "=r"((r)[3]) : "r"(addr))

__device__ __forceinline__ uint32_t pack2(__half lo, __half hi) {
    __half2 t(lo, hi);
    return *reinterpret_cast<uint32_t*>(&t);
}
__device__ __forceinline__ void split2(float x, __half& h, __half& l) {
    h = __float2half_rn(x);
    l = __float2half_rn(x - __half2float(h));
}

// ---- prepass: convert K (hi/lo) and V (fp16) into pre-swizzled tile images ----
// 1024 CTAs, each converts half a tile (better latency coverage).
__global__ __launch_bounds__(THREADS)
void prep(const float* __restrict__ k, const float* __restrict__ v) {
    const int tid = threadIdx.x;
    const int bx = blockIdx.x;
    const int tilei = bx >> 1, hf = bx & 1;
    const int bh = tilei >> 4, kb = tilei & 15;
    const size_t tile = (size_t)tilei * 8192;
    const float4* gk = (const float4*)(k + ((size_t)bh * SEQ + kb * 64) * DH);
    const float4* gv = (const float4*)(v + ((size_t)bh * SEQ + kb * 64) * DH);
    #pragma unroll
    for (int i = 0; i < 4; i++) {
        int f = hf * 512 + i * THREADS + tid;
        int row = f >> 4, c4 = f & 15;
        uint32_t off = (uint32_t)(row * 128 + (((c4 >> 1) ^ (row & 7)) << 4) + (c4 & 1) * 8);
        float4 kx = gk[f];
        __half h0, h1, h2, h3, l0, l1, l2, l3;
        split2(kx.x, h0, l0); split2(kx.y, h1, l1);
        split2(kx.z, h2, l2); split2(kx.w, h3, l3);
        *(uint2*)(g_kh + tile + off) = make_uint2(pack2(h0, h1), pack2(h2, h3));
        *(uint2*)(g_kl + tile + off) = make_uint2(pack2(l0, l1), pack2(l2, l3));
        float4 vx = gv[f];
        __half v0 = __float2half_rn(vx.x), v1 = __float2half_rn(vx.y);
        __half v2 = __float2half_rn(vx.z), v3 = __float2half_rn(vx.w);
        *(uint2*)(g_vv + tile + off) = make_uint2(pack2(v0, v1), pack2(v2, v3));
    }
}

// issue cp.async for one 24KB tile set (KH,KL,V) into smem buffer base
__device__ __forceinline__ void fetch_tiles(uint32_t bufb, size_t tile, int tid) {
    #pragma unroll
    for (int i = 0; i < 4; i++) {
        uint32_t c = (uint32_t)(i * 2048 + tid * 16);
        cp16(bufb + KH_O + c, g_kh + tile + c);
        cp16(bufb + KL_O + c, g_kl + tile + c);
        cp16(bufb + V_O  + c, g_vv + tile + c);
    }
    asm volatile("cp.async.commit_group;" ::: "memory");
}

__global__ __launch_bounds__(THREADS)
void sb_mma(const float* __restrict__ q, float* __restrict__ out) {
    extern __shared__ __align__(16) char smem[];
    const uint32_t sb = smem_u32(smem);
    const int tid = threadIdx.x;
    const int lane = tid & 31, warp = tid >> 5;
    const int q4 = lane & 3;                     // quad col idx
    const int sel = lane >> 3, rr = lane & 7;    // ldmatrix select / row

    // ---- chain-length-descending CTA mapping ----
    const int bh = blockIdx.x & 31;
    const int t = blockIdx.x >> 5;
    int mode, qb;                                 // 0=A (full), 1=U (upper), 2=L (lower)
    if (t == 0)      { mode = 0; qb = 7; }
    else if (t <= 8) { mode = 2; qb = t + 7; }
    else if (t == 9) { mode = 1; qb = 15; }
    else {
        int p = (t - 10) >> 1;
        if (((t - 10) & 1) == 0) { mode = 0; qb = 6 - p; }
        else                     { mode = 1; qb = 14 - p; }
    }
    const int kb_hi = (mode == 2) ? 7 : qb;
    const int kb_lo = (mode == 1) ? 8 : 0;
    const int qbase = qb * BQ;

    const float* qg = q + (size_t)bh * SEQ * DH;

    // ---- kick off cp.async for the first tile set into buf0 ----
    fetch_tiles(sb, (size_t)(bh * 16 + kb_hi) * 8192, tid);

    // ---- stage Q tile (fp16 hi/lo) into QH/QL, XOR-swizzled ----
    {
        const float4* gq = (const float4*)(qg + (size_t)qbase * DH);
        #pragma unroll
        for (int i = 0; i < 8; i++) {
            int f = i * THREADS + tid;
            int row = f >> 4, c4 = f & 15;
            float4 x = gq[f];
            __half h0, h1, h2, h3, l0, l1, l2, l3;
            split2(x.x, h0, l0); split2(x.y, h1, l1);
            split2(x.z, h2, l2); split2(x.w, h3, l3);
            uint32_t off = (uint32_t)(row * 128 + (((c4 >> 1) ^ (row & 7)) << 4) + (c4 & 1) * 8);
            *(uint2*)(smem + QH_O + off) = make_uint2(pack2(h0, h1), pack2(h2, h3));
            *(uint2*)(smem + QL_O + off) = make_uint2(pack2(l0, l1), pack2(l2, l3));
        }
    }
    __syncthreads();

    // ---- persistent Q A-fragments (hi & lo); QH/QL never overwritten ----
    uint32_t qh[4][4], ql[4][4];
    {
        int row = warp * 16 + (sel & 1) * 8 + rr;
        #pragma unroll
        for (int kc = 0; kc < 4; kc++) {
            int chunk = 2 * kc + (sel >> 1);
            uint32_t a = sb + (uint32_t)(row * 128 + ((chunk ^ rr) << 4));
            LDSM4(qh[kc], a + QH_O);
            LDSM4(ql[kc], a + QL_O);
        }
    }

    float o[8][4];
    #pragma unroll
    for (int nt = 0; nt < 8; nt++) { o[nt][0] = o[nt][1] = o[nt][2] = o[nt][3] = 0.f; }
    float P0 = 1.f, P1 = 1.f;                    // multiplicative carries
    const int wr0 = qbase + warp * 16 + (lane >> 2);
    const float SC = 0.18033688f;                // 0.125 * log2(e)

    #pragma unroll 1
    for (int kb = kb_hi; kb >= kb_lo; --kb) {
        const int kbase = kb * BK;
        const uint32_t bsb = sb + (uint32_t)(((kb_hi - kb) & 1) ? BUFSZ : 0);

        asm volatile("cp.async.wait_group 0;" ::: "memory");
        __syncthreads();   // current buf filled for all; prev buf reads all done

        // -- issue next tile set into the other buffer (covered by full body) --
        if (kb > kb_lo)
            fetch_tiles(sb + (uint32_t)(((kb_hi - kb) & 1) ? 0 : BUFSZ),
                        (size_t)(bh * 16 + kb - 1) * 8192, tid);

        // ---- QK^T: D[16 rows x 64 keys], 3 split passes ----
        float d[8][4];
        #pragma unroll
        for (int nt = 0; nt < 8; nt++) { d[nt][0] = d[nt][1] = d[nt][2] = d[nt][3] = 0.f; }

        #pragma unroll
        for (int kc = 0; kc < 4; kc++) {
            uint32_t kf[16];
            const int keyl = (sel >> 1) * 8 + rr;
            const int chunk = 2 * kc + (sel & 1);
            #pragma unroll
            for (int p = 0; p < 4; p++) {
                uint32_t a = bsb + KH_O + (uint32_t)((p * 16 + keyl) * 128 + ((chunk ^ rr) << 4));
                LDSM4(&kf[p * 4], a);
            }
            #pragma unroll
            for (int nt = 0; nt < 8; nt++) MMA(d[nt], qh[kc], kf[nt * 2], kf[nt * 2 + 1]);
            #pragma unroll
            for (int nt = 0; nt < 8; nt++) MMA(d[nt], ql[kc], kf[nt * 2], kf[nt * 2 + 1]);
            #pragma unroll
            for (int p = 0; p < 4; p++) {
                uint32_t a = bsb + KL_O + (uint32_t)((p * 16 + keyl) * 128 + ((chunk ^ rr) << 4));
                LDSM4(&kf[p * 4], a);
            }
            #pragma unroll
            for (int nt = 0; nt < 8; nt++) MMA(d[nt], qh[kc], kf[nt * 2], kf[nt * 2 + 1]);
        }

        // ---- interleaved scan + PV, kc descending (suffix order) ----
        // For each kc: issue V ldmatrix (latency hidden by scan MUFU),
        // scan keys of this kc (2 nt steps), then 8 PV MMAs.
        const bool diag = (kb == qb);
        #pragma unroll
        for (int kc = 3; kc >= 0; --kc) {
            uint32_t vf[16];
            const int keyv = kc * 16 + (sel & 1) * 8 + rr;
            #pragma unroll
            for (int p = 0; p < 4; p++) {
                int chunk = 2 * p + (sel >> 1);
                uint32_t a = bsb + V_O + (uint32_t)(keyv * 128 + ((chunk ^ rr) << 4));
                LDSM4T(&vf[p * 4], a);
            }

            uint32_t wf[4];
            #pragma unroll
            for (int nt = 2 * kc + 1; nt >= 2 * kc; --nt) {
                const int keyA = kbase + nt * 8 + 2 * q4;
                #pragma unroll
                for (int rs = 0; rs < 2; rs++) {
                    float x2a = d[nt][rs * 2 + 0] * SC;
                    float x2b = d[nt][rs * 2 + 1] * SC;
                    float ta = ex2f(-x2a), tb = ex2f(-x2b);
                    float za = rcpf(1.f + ta), zb = rcpf(1.f + tb);
                    float ba = 1.f - za, bb = 1.f - zb;
                    if (diag) {
                        const int rowg = wr0 + rs * 8;
                        if (keyA > rowg)     { za = 0.f; ba = 1.f; }
                        if (keyA + 1 > rowg) { zb = 0.f; bb = 1.f; }
                    }
                    float pp = ba * bb;
                    float u = pp;                               // inclusive suffix product
                    float t1 = __shfl_down_sync(FULL, u, 1, 4);
                    u = (q4 < 3) ? u * t1 : u;
                    float t2 = __shfl_down_sync(FULL, u, 2, 4);
                    u = (q4 < 2) ? u * t2 : u;
                    float ue = __shfl_down_sync(FULL, u, 1, 4); // exclusive (lanes above)
                    ue = (q4 < 3) ? ue : 1.f;
                    float tot = __shfl_sync(FULL, u, 0, 4);
                    float& P = rs ? P1 : P0;
                    float R  = P * ue;                          // betas of all higher keys
                    float Rb = bb * R;
                    float wb = zb * Rb;
                    float wa = za * ba * Rb;
                    P *= tot;
                    wf[(nt & 1) * 2 + rs] =
                        pack2(__float2half_rn(wa), __float2half_rn(wb));
                }
            }

            #pragma unroll
            for (int nt = 0; nt < 8; nt++) MMA(o[nt], wf, vf[nt * 2], vf[nt * 2 + 1]);
        }
    }

    // ---- write results ----
    if (mode == 2) {
        // Lower half: O_low (fp16) to scratch (rows wr0, wr0+8 are >= 512)
        __half* r0p = g_olow + ((size_t)bh * 512 + (wr0 - 512)) * DH;
        __half* r1p = g_olow + ((size_t)bh * 512 + (wr0 - 512 + 8)) * DH;
        #pragma unroll
        for (int nt = 0; nt < 8; nt++) {
            *(__half2*)(r0p + nt * 8 + 2 * q4) = __floats2half2_rn(o[nt][0], o[nt][1]);
            *(__half2*)(r1p + nt * 8 + 2 * q4) = __floats2half2_rn(o[nt][2], o[nt][3]);
        }
    } else {
        float* og = out + (size_t)bh * SEQ * DH;
        float* r0p = og + (size_t)wr0 * DH;
        float* r1p = og + (size_t)(wr0 + 8) * DH;
        #pragma unroll
        for (int nt = 0; nt < 8; nt++) {
            *(float2*)(r0p + nt * 8 + 2 * q4) = make_float2(o[nt][0], o[nt][1]);
            *(float2*)(r1p + nt * 8 + 2 * q4) = make_float2(o[nt][2], o[nt][3]);
        }
        if (mode == 1 && q4 == 0) {
            g_pup[bh * 512 + (wr0 - 512)] = P0;
            g_pup[bh * 512 + (wr0 - 512 + 8)] = P1;
        }
    }
}

// ---- combine: out[rows 512..1023] += P_up * O_low ----
__global__ __launch_bounds__(THREADS)
void comb(float* __restrict__ out) {
    const int x = blockIdx.x;            // bh*64 + rowgroup(8 rows)
    const int bh = x >> 6, rg = x & 63;
    const int tid = threadIdx.x;
    const int rl = tid >> 4, c = tid & 15;      // 8 rows x 16 cols(4 floats)
    const int row = rg * 8 + rl;                // 0..511 local
    const float p = g_pup[bh * 512 + row];
    const __half2* ol = (const __half2*)(g_olow + ((size_t)bh * 512 + row) * DH + c * 4);
    float2 fa = __half22float2(ol[0]);
    float2 fb = __half22float2(ol[1]);
    float4* op = (float4*)(out + ((size_t)bh * SEQ + 512 + row) * DH) + c;
    float4 ov = *op;
    ov.x += p * fa.x; ov.y += p * fa.y;
    ov.z += p * fb.x; ov.w += p * fb.y;
    *op = ov;
}

extern "C" void kernel_launch(void* const* d_in, const int* in_sizes, int n_in,
                              void* d_out, int out_size) {
    const float* q = (const float*)d_in[0];
    const float* k = (const float*)d_in[1];
    const float* v = (const float*)d_in[2];
    float* out = (float*)d_out;
    (void)in_sizes; (void)n_in; (void)out_size;

    prep<<<1024, THREADS>>>(k, v);   // pre-split/swizzle K,V tiles (half-tile CTAs)

    cudaFuncSetAttribute(sb_mma, cudaFuncAttributeMaxDynamicSharedMemorySize, SM_TOTAL);
    sb_mma<<<24 * 32, THREADS, SM_TOTAL>>>(q, out);   // 768 CTAs, longest chains first

    comb<<<32 * 64, THREADS>>>(out);  // merge split halves
}

// round 16
// speedup vs baseline: 1.0949x; 1.0478x over previous
#include <cuda_runtime.h>
#include <cuda_fp16.h>
#include <cstdint>

// Stickbreaking attention via mma.sync (HMMA) fp16-split. B=2 H=16 S=1024 D=64.
// Critical-path split: heavy q-tiles (qb>=8) run as TWO CTAs (Upper incl diag,
// Lower kb 0..7); comb: out += P_up * O_low (O_low fp16).
// Prepass pre-splits K (fp16 hi/lo) + V (fp16) into swizzled tile images.
// Q staged into buf1 (dead after fragment extraction) -> 48KB smem, 4 CTAs/SM.

#define SEQ 1024
#define DH 64
#define BQ 64
#define BK 64
#define THREADS 128
#define NQB (SEQ / BQ)
#define FULL 0xffffffffu

#define KH_O 0
#define KL_O 8192
#define V_O  16384
#define BUFSZ 24576
#define SM_TOTAL 49152

__device__ __align__(16) unsigned char g_kh[512 * 8192];
__device__ __align__(16) unsigned char g_kl[512 * 8192];
__device__ __align__(16) unsigned char g_vv[512 * 8192];
__device__ __align__(16) __half g_olow[32 * 512 * 64];
__device__ __align__(16) float g_pup[32 * 512];

__device__ __forceinline__ uint32_t smem_u32(const void* p) {
    uint32_t a;
    asm("{ .reg .u64 t; cvta.to.shared.u64 t, %1; cvt.u32.u64 %0, t; }" : "=r"(a) : "l"(p));
    return a;
}
__device__ __forceinline__ float ex2f(float x) {
    float r; asm("ex2.approx.f32 %0, %1;" : "=f"(r) : "f"(x)); return r;
}
__device__ __forceinline__ float rcpf(float x) {
    float r; asm("rcp.approx.f32 %0, %1;" : "=f"(r) : "f"(x)); return r;
}
__device__ __forceinline__ void cp16(uint32_t dst, const void* src) {
    asm volatile("cp.async.cg.shared.global [%0], [%1], 16;" :: "r"(dst), "l"(src));
}

#define MMA(d, a, b0, b1) \
    asm volatile("mma.sync.aligned.m16n8k16.row.col.f32.f16.f16.f32 " \
        "{%0,%1,%2,%3}, {%4,%5,%6,%7}, {%8,%9}, {%0,%1,%2,%3};" \
        : "+f"((d)[0]), "+f"((d)[1]), "+f"((d)[2]), "+f"((d)[3]) \
        : "r"((a)[0]), "r"((a)[1]), "r"((a)[2]), "r"((a)[3]), "r"(b0), "r"(b1))

#define LDSM4(r, addr) \
    asm volatile("ldmatrix.sync.aligned.m8n8.x4.shared.b16 {%0,%1,%2,%3}, [%4];" \
        : "=r"((r)[0]), "=r"((r)[1]), "=r"((r)[2]), "=r"((r)[3]) : "r"(addr))

#define LDSM4T(r, addr) \
    asm volatile("ldmatrix.sync.aligned.m8n8.x4.trans.shared.b16 {%0,%1,%2,%3}, [%4];" \
        : "=r"((r)[0]), "=r"((r)[1]), "=r"((r)[2]), "=r"((r)[3]) : "r"(addr))

__device__ __forceinline__ uint32_t pack2(__half lo, __half hi) {
    __half2 t(lo, hi);
    return *reinterpret_cast<uint32_t*>(&t);
}
__device__ __forceinline__ void split2(float x, __half& h, __half& l) {
    h = __float2half_rn(x);
    l = __float2half_rn(x - __half2float(h));
}

// ---- prepass: K (hi/lo) + V (fp16) into pre-swizzled tile images ----
// 2048 CTAs, quarter tile each (latency-bound: maximize parallelism).
__global__ __launch_bounds__(THREADS)
void prep(const float* __restrict__ k, const float* __restrict__ v) {
    const int tid = threadIdx.x;
    const int bx = blockIdx.x;
    const int tilei = bx >> 2, qf = bx & 3;
    const int bh = tilei >> 4, kb = tilei & 15;
    const size_t tile = (size_t)tilei * 8192;
    const float4* gk = (const float4*)(k + ((size_t)bh * SEQ + kb * 64) * DH);
    const float4* gv = (const float4*)(v + ((size_t)bh * SEQ + kb * 64) * DH);
    #pragma unroll
    for (int i = 0; i < 2; i++) {
        int f = qf * 256 + i * THREADS + tid;
        int row = f >> 4, c4 = f & 15;
        uint32_t off = (uint32_t)(row * 128 + (((c4 >> 1) ^ (row & 7)) << 4) + (c4 & 1) * 8);
        float4 kx = gk[f];
        __half h0, h1, h2, h3, l0, l1, l2, l3;
        split2(kx.x, h0, l0); split2(kx.y, h1, l1);
        split2(kx.z, h2, l2); split2(kx.w, h3, l3);
        *(uint2*)(g_kh + tile + off) = make_uint2(pack2(h0, h1), pack2(h2, h3));
        *(uint2*)(g_kl + tile + off) = make_uint2(pack2(l0, l1), pack2(l2, l3));
        float4 vx = gv[f];
        __half v0 = __float2half_rn(vx.x), v1 = __float2half_rn(vx.y);
        __half v2 = __float2half_rn(vx.z), v3 = __float2half_rn(vx.w);
        *(uint2*)(g_vv + tile + off) = make_uint2(pack2(v0, v1), pack2(v2, v3));
    }
}

// issue cp.async for one 24KB tile set (KH,KL,V) into smem buffer base
__device__ __forceinline__ void fetch_tiles(uint32_t bufb, size_t tile, int tid) {
    #pragma unroll
    for (int i = 0; i < 4; i++) {
        uint32_t c = (uint32_t)(i * 2048 + tid * 16);
        cp16(bufb + KH_O + c, g_kh + tile + c);
        cp16(bufb + KL_O + c, g_kl + tile + c);
        cp16(bufb + V_O  + c, g_vv + tile + c);
    }
    asm volatile("cp.async.commit_group;" ::: "memory");
}

__global__ __launch_bounds__(THREADS, 4)
void sb_mma(const float* __restrict__ q, float* __restrict__ out) {
    extern __shared__ __align__(16) char smem[];
    const uint32_t sb = smem_u32(smem);
    const int tid = threadIdx.x;
    const int lane = tid & 31, warp = tid >> 5;
    const int q4 = lane & 3;                     // quad col idx
    const int sel = lane >> 3, rr = lane & 7;    // ldmatrix select / row

    // ---- chain-length-descending CTA mapping ----
    const int bh = blockIdx.x & 31;
    const int t = blockIdx.x >> 5;
    int mode, qb;                                 // 0=A (full), 1=U (upper), 2=L (lower)
    if (t == 0)      { mode = 0; qb = 7; }
    else if (t <= 8) { mode = 2; qb = t + 7; }
    else if (t == 9) { mode = 1; qb = 15; }
    else {
        int p = (t - 10) >> 1;
        if (((t - 10) & 1) == 0) { mode = 0; qb = 6 - p; }
        else                     { mode = 1; qb = 14 - p; }
    }
    const int kb_hi = (mode == 2) ? 7 : qb;
    const int kb_lo = (mode == 1) ? 8 : 0;
    const int qbase = qb * BQ;

    const float* qg = q + (size_t)bh * SEQ * DH;

    // ---- kick off cp.async for the first tile set into buf0 ----
    fetch_tiles(sb, (size_t)(bh * 16 + kb_hi) * 8192, tid);

    // ---- stage Q tile (fp16 hi/lo) into buf1 area (dead after extraction) ----
    {
        const float4* gq = (const float4*)(qg + (size_t)qbase * DH);
        #pragma unroll
        for (int i = 0; i < 8; i++) {
            int f = i * THREADS + tid;
            int row = f >> 4, c4 = f & 15;
            float4 x = gq[f];
            __half h0, h1, h2, h3, l0, l1, l2, l3;
            split2(x.x, h0, l0); split2(x.y, h1, l1);
            split2(x.z, h2, l2); split2(x.w, h3, l3);
            uint32_t off = (uint32_t)(row * 128 + (((c4 >> 1) ^ (row & 7)) << 4) + (c4 & 1) * 8);
            *(uint2*)(smem + BUFSZ + off) = make_uint2(pack2(h0, h1), pack2(h2, h3));
            *(uint2*)(smem + BUFSZ + 8192 + off) = make_uint2(pack2(l0, l1), pack2(l2, l3));
        }
    }
    __syncthreads();

    // ---- persistent Q A-fragments (hi & lo) extracted to registers ----
    uint32_t qh[4][4], ql[4][4];
    {
        int row = warp * 16 + (sel & 1) * 8 + rr;
        #pragma unroll
        for (int kc = 0; kc < 4; kc++) {
            int chunk = 2 * kc + (sel >> 1);
            uint32_t a = sb + BUFSZ + (uint32_t)(row * 128 + ((chunk ^ rr) << 4));
            LDSM4(qh[kc], a);
            LDSM4(ql[kc], a + 8192);
        }
    }

    float o[8][4];
    #pragma unroll
    for (int nt = 0; nt < 8; nt++) { o[nt][0] = o[nt][1] = o[nt][2] = o[nt][3] = 0.f; }
    float P0 = 1.f, P1 = 1.f;                    // multiplicative carries
    const int wr0 = qbase + warp * 16 + (lane >> 2);
    const float SC = 0.18033688f;                // 0.125 * log2(e)

    #pragma unroll 1
    for (int kb = kb_hi; kb >= kb_lo; --kb) {
        const int kbase = kb * BK;
        const uint32_t bsb = sb + (uint32_t)(((kb_hi - kb) & 1) ? BUFSZ : 0);

        asm volatile("cp.async.wait_group 0;" ::: "memory");
        __syncthreads();   // current buf filled; prev buf reads + Q extraction done

        // -- issue next tile set into the other buffer (covered by full body) --
        if (kb > kb_lo)
            fetch_tiles(sb + (uint32_t)(((kb_hi - kb) & 1) ? 0 : BUFSZ),
                        (size_t)(bh * 16 + kb - 1) * 8192, tid);

        // ---- QK^T: D[16 rows x 64 keys], 3 split passes ----
        float d[8][4];
        #pragma unroll
        for (int nt = 0; nt < 8; nt++) { d[nt][0] = d[nt][1] = d[nt][2] = d[nt][3] = 0.f; }

        #pragma unroll
        for (int kc = 0; kc < 4; kc++) {
            uint32_t kf[16];
            const int keyl = (sel >> 1) * 8 + rr;
            const int chunk = 2 * kc + (sel & 1);
            #pragma unroll
            for (int p = 0; p < 4; p++) {
                uint32_t a = bsb + KH_O + (uint32_t)((p * 16 + keyl) * 128 + ((chunk ^ rr) << 4));
                LDSM4(&kf[p * 4], a);
            }
            #pragma unroll
            for (int nt = 0; nt < 8; nt++) MMA(d[nt], qh[kc], kf[nt * 2], kf[nt * 2 + 1]);
            #pragma unroll
            for (int nt = 0; nt < 8; nt++) MMA(d[nt], ql[kc], kf[nt * 2], kf[nt * 2 + 1]);
            #pragma unroll
            for (int p = 0; p < 4; p++) {
                uint32_t a = bsb + KL_O + (uint32_t)((p * 16 + keyl) * 128 + ((chunk ^ rr) << 4));
                LDSM4(&kf[p * 4], a);
            }
            #pragma unroll
            for (int nt = 0; nt < 8; nt++) MMA(d[nt], qh[kc], kf[nt * 2], kf[nt * 2 + 1]);
        }

        // ---- interleaved scan + PV, kc descending (suffix order) ----
        const bool diag = (kb == qb);
        #pragma unroll
        for (int kc = 3; kc >= 0; --kc) {
            uint32_t vf[16];
            const int keyv = kc * 16 + (sel & 1) * 8 + rr;
            #pragma unroll
            for (int p = 0; p < 4; p++) {
                int chunk = 2 * p + (sel >> 1);
                uint32_t a = bsb + V_O + (uint32_t)(keyv * 128 + ((chunk ^ rr) << 4));
                LDSM4T(&vf[p * 4], a);
            }

            uint32_t wf[4];
            #pragma unroll
            for (int nt = 2 * kc + 1; nt >= 2 * kc; --nt) {
                const int keyA = kbase + nt * 8 + 2 * q4;
                #pragma unroll
                for (int rs = 0; rs < 2; rs++) {
                    float x2a = d[nt][rs * 2 + 0] * SC;
                    float x2b = d[nt][rs * 2 + 1] * SC;
                    float ta = ex2f(-x2a), tb = ex2f(-x2b);
                    float za = rcpf(1.f + ta), zb = rcpf(1.f + tb);
                    float ba = 1.f - za, bb = 1.f - zb;
                    if (diag) {
                        const int rowg = wr0 + rs * 8;
                        if (keyA > rowg)     { za = 0.f; ba = 1.f; }
                        if (keyA + 1 > rowg) { zb = 0.f; bb = 1.f; }
                    }
                    float pp = ba * bb;
                    float u = pp;                               // inclusive suffix product
                    float t1 = __shfl_down_sync(FULL, u, 1, 4);
                    u = (q4 < 3) ? u * t1 : u;
                    float t2 = __shfl_down_sync(FULL, u, 2, 4);
                    u = (q4 < 2) ? u * t2 : u;
                    float ue = __shfl_down_sync(FULL, u, 1, 4); // exclusive (lanes above)
                    ue = (q4 < 3) ? ue : 1.f;
                    float tot = __shfl_sync(FULL, u, 0, 4);
                    float& P = rs ? P1 : P0;
                    float R  = P * ue;                          // betas of all higher keys
                    float Rb = bb * R;
                    float wb = zb * Rb;
                    float wa = za * ba * Rb;
                    P *= tot;
                    wf[(nt & 1) * 2 + rs] =
                        pack2(__float2half_rn(wa), __float2half_rn(wb));
                }
            }

            #pragma unroll
            for (int nt = 0; nt < 8; nt++) MMA(o[nt], wf, vf[nt * 2], vf[nt * 2 + 1]);
        }
    }

    // ---- write results ----
    if (mode == 2) {
        __half* r0p = g_olow + ((size_t)bh * 512 + (wr0 - 512)) * DH;
        __half* r1p = g_olow + ((size_t)bh * 512 + (wr0 - 512 + 8)) * DH;
        #pragma unroll
        for (int nt = 0; nt < 8; nt++) {
            *(__half2*)(r0p + nt * 8 + 2 * q4) = __floats2half2_rn(o[nt][0], o[nt][1]);
            *(__half2*)(r1p + nt * 8 + 2 * q4) = __floats2half2_rn(o[nt][2], o[nt][3]);
        }
    } else {
        float* og = out + (size_t)bh * SEQ * DH;
        float* r0p = og + (size_t)wr0 * DH;
        float* r1p = og + (size_t)(wr0 + 8) * DH;
        #pragma unroll
        for (int nt = 0; nt < 8; nt++) {
            *(float2*)(r0p + nt * 8 + 2 * q4) = make_float2(o[nt][0], o[nt][1]);
            *(float2*)(r1p + nt * 8 + 2 * q4) = make_float2(o[nt][2], o[nt][3]);
        }
        if (mode == 1 && q4 == 0) {
            g_pup[bh * 512 + (wr0 - 512)] = P0;
            g_pup[bh * 512 + (wr0 - 512 + 8)] = P1;
        }
    }
}

// ---- combine: out[rows 512..1023] += P_up * O_low ----
__global__ __launch_bounds__(THREADS)
void comb(float* __restrict__ out) {
    const int x = blockIdx.x;            // bh*64 + rowgroup(8 rows)
    const int bh = x >> 6, rg = x & 63;
    const int tid = threadIdx.x;
    const int rl = tid >> 4, c = tid & 15;      // 8 rows x 16 cols(4 floats)
    const int row = rg * 8 + rl;                // 0..511 local
    const float p = g_pup[bh * 512 + row];
    const __half2* ol = (const __half2*)(g_olow + ((size_t)bh * 512 + row) * DH + c * 4);
    float2 fa = __half22float2(ol[0]);
    float2 fb = __half22float2(ol[1]);
    float4* op = (float4*)(out + ((size_t)bh * SEQ + 512 + row) * DH) + c;
    float4 ov = *op;
    ov.x += p * fa.x; ov.y += p * fa.y;
    ov.z += p * fb.x; ov.w += p * fb.y;
    *op = ov;
}

extern "C" void kernel_launch(void* const* d_in, const int* in_sizes, int n_in,
                              void* d_out, int out_size) {
    const float* q = (const float*)d_in[0];
    const float* k = (const float*)d_in[1];
    const float* v = (const float*)d_in[2];
    float* out = (float*)d_out;
    (void)in_sizes; (void)n_in; (void)out_size;

    prep<<<2048, THREADS>>>(k, v);   // quarter-tile CTAs: latency-bound, go wide

    cudaFuncSetAttribute(sb_mma, cudaFuncAttributeMaxDynamicSharedMemorySize, SM_TOTAL);
    sb_mma<<<24 * 32, THREADS, SM_TOTAL>>>(q, out);   // 768 CTAs, longest chains first

    comb<<<32 * 64, THREADS>>>(out);  // merge split halves
}